// round 3
// baseline (speedup 1.0000x reference)
#include <cuda_runtime.h>
#include <math.h>

// GCN1: 3-layer GCN over 4 graphs, shared weights, scalar-mean output.
// Per graph: device-side CSR build (hist -> scan -> scatter), then
// 3x [ SpMM(block-per-dst, CSR) -> GEMM(+bias,relu) ]; last GEMM fuses a
// global double-precision sum for the final scalar mean.
//
// RULE: __device__ scratch symbols are ONLY referenced inside device code.
// Kernel args are exclusively harness pointers + scalars.

#define NN 50000
#define EE 800000
#define FH 304
#define FI 128

// ---- scratch (__device__ globals; never passed as kernel args) ----
__device__ float g_bufA[(size_t)NN * FH];   // SpMM output m
__device__ float g_bufB[(size_t)NN * FH];   // GEMM output y (input to next SpMM)
__device__ float g_ns[NN];                  // out-degree norm (for src)
__device__ float g_nd[NN];                  // in-degree norm (for dst)
__device__ int   g_deg_src[NN];
__device__ int   g_deg_dst[NN];
__device__ int   g_rowoff[NN + 1];
__device__ int   g_cursor[NN];
__device__ int   g_csr_src[EE];
__device__ double g_sum;

__global__ void k_init() { g_sum = 0.0; }

__global__ void k_zero_deg() {
    int i = blockIdx.x * blockDim.x + threadIdx.x;
    if (i < NN) { g_deg_src[i] = 0; g_deg_dst[i] = 0; }
}

__global__ void k_deg(const int* __restrict__ src, const int* __restrict__ dst) {
    int e = blockIdx.x * blockDim.x + threadIdx.x;
    if (e < EE) {
        atomicAdd(&g_deg_src[src[e]], 1);
        atomicAdd(&g_deg_dst[dst[e]], 1);
    }
}

// One block of 1024 threads: exclusive scan of in-degrees -> rowoff/cursor,
// plus both degree norms.
__global__ void k_scan() {
    const int T = 1024;
    int t = threadIdx.x;
    const int CH = (NN + T - 1) / T;  // 49
    int beg = t * CH;
    int end = min(beg + CH, NN);
    int lsum = 0;
    for (int i = beg; i < end; i++) lsum += g_deg_dst[i];
    __shared__ int sm[T];
    sm[t] = lsum;
    __syncthreads();
    for (int off = 1; off < T; off <<= 1) {
        int v = (t >= off) ? sm[t - off] : 0;
        __syncthreads();
        sm[t] += v;
        __syncthreads();
    }
    int run = sm[t] - lsum;  // exclusive prefix of this thread's chunk
    for (int i = beg; i < end; i++) {
        int c = g_deg_dst[i];
        g_rowoff[i] = run;
        g_cursor[i] = run;
        run += c;
        g_nd[i] = rsqrtf((float)max(c, 1));
        g_ns[i] = rsqrtf((float)max(g_deg_src[i], 1));
    }
    if (t == T - 1) g_rowoff[NN] = run;
}

__global__ void k_scatter(const int* __restrict__ src, const int* __restrict__ dst) {
    int e = blockIdx.x * blockDim.x + threadIdx.x;
    if (e < EE) {
        int d = dst[e];
        int p = atomicAdd(&g_cursor[d], 1);
        g_csr_src[p] = src[e];
    }
}

// Block-per-dst SpMM: g_bufA[n][:] = nd[n] * sum_{s in in(n)} ns[s] * hin[s][:]
// hin = xext (layer 1) or g_bufB (layers 2,3). 128 threads per block; each
// thread owns features {t, t+128, t+256} as applicable.
__global__ void k_spmm(const float* __restrict__ xext, int use_ext, int F) {
    const float* __restrict__ hin = use_ext ? xext : (const float*)g_bufB;
    int n = blockIdx.x;
    int t = threadIdx.x;
    int beg = g_rowoff[n];
    int end = g_rowoff[n + 1];
    float acc0 = 0.f, acc1 = 0.f, acc2 = 0.f;
    for (int j = beg; j < end; j++) {
        int s = g_csr_src[j];
        float w = g_ns[s];
        const float* r = hin + (size_t)s * F;
        acc0 += w * r[t];
        if (F > 128) {
            acc1 += w * r[t + 128];
            if (t + 256 < F) acc2 += w * r[t + 256];
        }
    }
    float nd = g_nd[n];
    float* o = g_bufA + (size_t)n * F;
    o[t] = acc0 * nd;
    if (F > 128) {
        o[t + 128] = acc1 * nd;
        if (t + 256 < F) o[t + 256] = acc2 * nd;
    }
}

// Tiled fp32 GEMM: g_bufB = relu(g_bufA[M,K] @ W[K,FH] + bias); optional
// fused global sum into g_sum.
#define BM 64
#define BN 64
#define BK 16
__global__ void k_gemm(const float* __restrict__ B, const float* __restrict__ bias,
                       int K, int dosum) {
    const int M = NN, N = FH;
    const float* __restrict__ A = (const float*)g_bufA;
    float* __restrict__ C = g_bufB;

    __shared__ float As[BK][BM + 1];
    __shared__ float Bs[BK][BN];
    int tid = threadIdx.x;            // 256 threads
    int ty = tid >> 4, tx = tid & 15; // 16x16
    int rowBase = blockIdx.x * BM;
    int colBase = blockIdx.y * BN;
    float acc[4][4];
#pragma unroll
    for (int i = 0; i < 4; i++)
#pragma unroll
        for (int j = 0; j < 4; j++) acc[i][j] = 0.f;

    for (int k0 = 0; k0 < K; k0 += BK) {
        for (int i = tid; i < BM * BK; i += 256) {
            int m = i / BK, kk = i % BK;
            int gr = rowBase + m;
            As[kk][m] = (gr < M) ? A[(size_t)gr * K + k0 + kk] : 0.f;
        }
        for (int i = tid; i < BK * BN; i += 256) {
            int kk = i / BN, n = i % BN;
            int gc = colBase + n;
            Bs[kk][n] = (gc < N) ? B[(size_t)(k0 + kk) * N + gc] : 0.f;
        }
        __syncthreads();
#pragma unroll
        for (int kk = 0; kk < BK; kk++) {
            float a[4], b[4];
#pragma unroll
            for (int i = 0; i < 4; i++) a[i] = As[kk][ty * 4 + i];
#pragma unroll
            for (int j = 0; j < 4; j++) b[j] = Bs[kk][tx * 4 + j];
#pragma unroll
            for (int i = 0; i < 4; i++)
#pragma unroll
                for (int j = 0; j < 4; j++) acc[i][j] += a[i] * b[j];
        }
        __syncthreads();
    }

    float lsum = 0.f;
#pragma unroll
    for (int i = 0; i < 4; i++) {
        int r = rowBase + ty * 4 + i;
#pragma unroll
        for (int j = 0; j < 4; j++) {
            int c = colBase + tx * 4 + j;
            if (r < M && c < N) {
                float v = acc[i][j] + bias[c];
                v = fmaxf(v, 0.f);
                C[(size_t)r * N + c] = v;
                lsum += v;
            }
        }
    }
    if (dosum) {
#pragma unroll
        for (int off = 16; off > 0; off >>= 1)
            lsum += __shfl_down_sync(0xffffffffu, lsum, off);
        __shared__ float wsum[8];
        int lane = tid & 31, wid = tid >> 5;
        if (lane == 0) wsum[wid] = lsum;
        __syncthreads();
        if (tid == 0) {
            float tot = 0.f;
#pragma unroll
            for (int w = 0; w < 8; w++) tot += wsum[w];
            atomicAdd(&g_sum, (double)tot);
        }
    }
}

__global__ void k_final(float* __restrict__ out) {
    out[0] = (float)(g_sum / (4.0 * NN * FH));
}

extern "C" void kernel_launch(void* const* d_in, const int* in_sizes, int n_in,
                              void* d_out, int out_size) {
    // Classify inputs by element count (robust to metadata ordering):
    //   6,400,000 -> x (appearance order x1..x4)
    //     800,000 -> edge arrays; pairs in appearance order = (src_i, dst_i)
    //      38,912 -> W1;  92,416 -> W2 then W3;  304 -> b1, b2, b3
    const float* X[4];   int nx = 0;
    const int*   EDG[8]; int ne = 0;
    const float* W[3] = {0, 0, 0};
    const float* Bv[3]; int nb = 0;
    int nw2 = 0;
    for (int i = 0; i < n_in; i++) {
        int sz = in_sizes[i];
        if (sz == 6400000)      X[nx++]  = (const float*)d_in[i];
        else if (sz == 800000)  EDG[ne++] = (const int*)d_in[i];
        else if (sz == 38912)   W[0] = (const float*)d_in[i];
        else if (sz == 92416)   { W[1 + nw2] = (const float*)d_in[i]; nw2++; }
        else if (sz == 304)     Bv[nb++] = (const float*)d_in[i];
    }
    float* out = (float*)d_out;

    k_init<<<1, 1>>>();

    dim3 gemmGrid((NN + BM - 1) / BM, (FH + BN - 1) / BN);  // 782 x 5

    for (int g = 0; g < 4; g++) {
        const int* src = EDG[2 * g];
        const int* dst = EDG[2 * g + 1];

        k_zero_deg<<<(NN + 255) / 256, 256>>>();
        k_deg<<<(EE + 255) / 256, 256>>>(src, dst);
        k_scan<<<1, 1024>>>();
        k_scatter<<<(EE + 255) / 256, 256>>>(src, dst);

        // layer 1: SpMM at F=128, then GEMM K=128
        k_spmm<<<NN, 128>>>(X[g], 1, FI);
        k_gemm<<<gemmGrid, 256>>>(W[0], Bv[0], FI, 0);
        // layer 2
        k_spmm<<<NN, 128>>>(X[g], 0, FH);
        k_gemm<<<gemmGrid, 256>>>(W[1], Bv[1], FH, 0);
        // layer 3 (+ fused global sum)
        k_spmm<<<NN, 128>>>(X[g], 0, FH);
        k_gemm<<<gemmGrid, 256>>>(W[2], Bv[2], FH, 1);
    }

    k_final<<<1, 1>>>(out);
}

// round 6
// speedup vs baseline: 2.6403x; 2.6403x over previous
#include <cuda_runtime.h>
#include <math.h>
#include <stdint.h>

// GCN1: 3-layer GCN over 4 graphs, shared weights, scalar-mean output.
// R5: tf32 mma.sync GEMM (tcgen05 unavailable: harness PTX targets sm_103,
//     not sm_103a). Batched CSR build + parallel scan. SpMM per-graph
//     (keeps the gather working set L2-resident).

#define NN 50000
#define EE 800000
#define FH 304
#define FI 128
#define NG 4
#define NB 196   // ceil(NN/256)

// ---------------- scratch (__device__ only; never passed as kernel args) ----
__device__ __align__(128) float g_bufA[(size_t)NN * FH];
__device__ __align__(128) float g_bufB[(size_t)NN * FH];
__device__ __align__(128) float g_Wt1[320 * 128];   // [Npad=320][Kp]  K-major
__device__ __align__(128) float g_Wt2[320 * 320];
__device__ __align__(128) float g_Wt3[320 * 320];
__device__ float g_ns[NG][NN];
__device__ float g_nd[NG][NN];
__device__ int   g_deg_s[NG][NN];
__device__ int   g_deg_d[NG][NN];
__device__ int   g_rowoff[NG][NN + 1];
__device__ int   g_cursor[NG][NN];
__device__ int   g_csr[NG][EE];
__device__ int   g_bsum[NG][256];
__device__ int   g_boff[NG][256];
__device__ double g_sum;

// ---------------- small kernels ---------------------------------------------
__global__ void k_init() { g_sum = 0.0; }

// transpose W[K][FH] -> Wt[Npad=320][Kp], zero-padded in both dims
__global__ void k_prep_w(const float* __restrict__ W, int sel, int K, int Kp) {
    int id = blockIdx.x * blockDim.x + threadIdx.x;
    if (id >= 320 * Kp) return;
    int n = id / Kp, k = id % Kp;
    float v = (k < K && n < FH) ? W[(size_t)k * FH + n] : 0.f;
    float* dst = (sel == 0) ? g_Wt1 : (sel == 1) ? g_Wt2 : g_Wt3;
    dst[(size_t)n * Kp + k] = v;
}

__global__ void k_zero() {
    int g = blockIdx.y;
    int i = blockIdx.x * blockDim.x + threadIdx.x;
    if (i < NN) { g_deg_s[g][i] = 0; g_deg_d[g][i] = 0; }
}

__global__ void k_deg(const int* __restrict__ s0, const int* __restrict__ d0,
                      const int* __restrict__ s1, const int* __restrict__ d1,
                      const int* __restrict__ s2, const int* __restrict__ d2,
                      const int* __restrict__ s3, const int* __restrict__ d3) {
    int g = blockIdx.y;
    const int* s = (g == 0) ? s0 : (g == 1) ? s1 : (g == 2) ? s2 : s3;
    const int* d = (g == 0) ? d0 : (g == 1) ? d1 : (g == 2) ? d2 : d3;
    int e = blockIdx.x * blockDim.x + threadIdx.x;
    if (e < EE) {
        atomicAdd(&g_deg_s[g][s[e]], 1);
        atomicAdd(&g_deg_d[g][d[e]], 1);
    }
}

__global__ void k_scan1() {
    int g = blockIdx.y, t = threadIdx.x;
    int i = blockIdx.x * 256 + t;
    __shared__ int sm[256];
    sm[t] = (i < NN) ? g_deg_d[g][i] : 0;
    __syncthreads();
    for (int o = 128; o > 0; o >>= 1) {
        if (t < o) sm[t] += sm[t + o];
        __syncthreads();
    }
    if (t == 0) g_bsum[g][blockIdx.x] = sm[0];
}

__global__ void k_scan2() {
    int g = blockIdx.y, t = threadIdx.x;
    int v = (t < NB) ? g_bsum[g][t] : 0;
    __shared__ int sm[256];
    sm[t] = v;
    __syncthreads();
    for (int o = 1; o < 256; o <<= 1) {
        int a = (t >= o) ? sm[t - o] : 0;
        __syncthreads();
        sm[t] += a;
        __syncthreads();
    }
    g_boff[g][t] = sm[t] - v;  // exclusive
}

__global__ void k_scan3() {
    int g = blockIdx.y, t = threadIdx.x;
    int i = blockIdx.x * 256 + t;
    int d = (i < NN) ? g_deg_d[g][i] : 0;
    __shared__ int sm[256];
    sm[t] = d;
    __syncthreads();
    for (int o = 1; o < 256; o <<= 1) {
        int a = (t >= o) ? sm[t - o] : 0;
        __syncthreads();
        sm[t] += a;
        __syncthreads();
    }
    int off = g_boff[g][blockIdx.x] + sm[t] - d;  // exclusive
    if (i < NN) {
        g_rowoff[g][i] = off;
        g_cursor[g][i] = off;
        g_nd[g][i] = rsqrtf((float)max(d, 1));
        g_ns[g][i] = rsqrtf((float)max(g_deg_s[g][i], 1));
    }
    if (blockIdx.x == 0 && t == 0) g_rowoff[g][NN] = EE;
}

__global__ void k_scatter(const int* __restrict__ s0, const int* __restrict__ d0,
                          const int* __restrict__ s1, const int* __restrict__ d1,
                          const int* __restrict__ s2, const int* __restrict__ d2,
                          const int* __restrict__ s3, const int* __restrict__ d3) {
    int g = blockIdx.y;
    const int* s = (g == 0) ? s0 : (g == 1) ? s1 : (g == 2) ? s2 : s3;
    const int* d = (g == 0) ? d0 : (g == 1) ? d1 : (g == 2) ? d2 : d3;
    int e = blockIdx.x * blockDim.x + threadIdx.x;
    if (e < EE) {
        int p = atomicAdd(&g_cursor[g][d[e]], 1);
        g_csr[g][p] = s[e];
    }
}

// Block-per-dst SpMM: g_bufA[n][:] = nd[n] * sum_{s in in(n)} ns[s]*hin[s][:]
__global__ void k_spmm(const float* __restrict__ xext, int use_ext, int F, int g) {
    const float* __restrict__ hin = use_ext ? xext : (const float*)g_bufB;
    int n = blockIdx.x;
    int t = threadIdx.x;
    int beg = g_rowoff[g][n];
    int end = g_rowoff[g][n + 1];
    float acc0 = 0.f, acc1 = 0.f, acc2 = 0.f;
    int j = beg;
    for (; j + 1 < end; j += 2) {
        int sA = g_csr[g][j], sB = g_csr[g][j + 1];
        float wA = g_ns[g][sA], wB = g_ns[g][sB];
        const float* rA = hin + (size_t)sA * F;
        const float* rB = hin + (size_t)sB * F;
        acc0 += wA * rA[t] + wB * rB[t];
        if (F > 128) {
            acc1 += wA * rA[t + 128] + wB * rB[t + 128];
            if (t + 256 < F) acc2 += wA * rA[t + 256] + wB * rB[t + 256];
        }
    }
    if (j < end) {
        int s = g_csr[g][j];
        float w = g_ns[g][s];
        const float* r = hin + (size_t)s * F;
        acc0 += w * r[t];
        if (F > 128) {
            acc1 += w * r[t + 128];
            if (t + 256 < F) acc2 += w * r[t + 256];
        }
    }
    float nd = g_nd[g][n];
    float* o = g_bufA + (size_t)n * F;
    o[t] = acc0 * nd;
    if (F > 128) {
        o[t + 128] = acc1 * nd;
        if (t + 256 < F) o[t + 256] = acc2 * nd;
    }
}

// ---------------- tf32 mma.sync GEMM ----------------------------------------
// g_bufB[50000 x 304] = relu(g_bufA[.,K] @ Wt^T + bias), optional fused sum.
// CTA: 256 thr (8 warps, 4x2), tile 128x64, BK=32 tf32. mma.m16n8k8.
__device__ __forceinline__ uint32_t f2tf32(float v) {
    uint32_t o;
    asm("cvt.rna.tf32.f32 %0, %1;" : "=r"(o) : "f"(v));
    return o;
}
__device__ __forceinline__ void mma8(float* d, const uint32_t* a, const uint32_t* b) {
    asm volatile("mma.sync.aligned.m16n8k8.row.col.f32.tf32.tf32.f32 "
                 "{%0,%1,%2,%3}, {%4,%5,%6,%7}, {%8,%9}, {%0,%1,%2,%3};"
                 : "+f"(d[0]), "+f"(d[1]), "+f"(d[2]), "+f"(d[3])
                 : "r"(a[0]), "r"(a[1]), "r"(a[2]), "r"(a[3]),
                   "r"(b[0]), "r"(b[1]));
}

#define PADK 36  // 32 + 4 pad: fragment LDS bank = (4g+c)%32, conflict-free

__global__ void __launch_bounds__(256)
k_gemm_mma(const float* __restrict__ bias, int wsel, int K, int NC, int dosum) {
    __shared__ uint32_t As[128][PADK];
    __shared__ uint32_t Bs[64][PADK];
    __shared__ float wsum[8];

    const float* __restrict__ Wt = (wsel == 0) ? g_Wt1 : (wsel == 1) ? g_Wt2 : g_Wt3;
    const int Kp = NC * 32;
    const int astride = K;  // g_bufA stride equals actual K (128 or 304)

    int tid = threadIdx.x, wid = tid >> 5, lane = tid & 31;
    int wm = wid & 3, wn = wid >> 2;              // warp 4x2
    int rowBase = blockIdx.x * 128;
    int colBase = blockIdx.y * 64;

    float acc[2][4][4];
#pragma unroll
    for (int mi = 0; mi < 2; mi++)
#pragma unroll
        for (int ni = 0; ni < 4; ni++)
#pragma unroll
            for (int q = 0; q < 4; q++) acc[mi][ni][q] = 0.f;

    int arow = tid >> 3, aq = tid & 7;            // A: 4 float4 per thread
    int brow = tid >> 3, bq = tid & 7;            // B: 2 float4 per thread
    float4 aR[4], bR[2];

    // prefetch chunk 0
    {
        int k0 = 0;
#pragma unroll
        for (int j = 0; j < 4; j++) {
            int r = arow + j * 32, gr = rowBase + r, kf = k0 + aq * 4;
            aR[j] = (gr < NN && kf < K)
                ? *(const float4*)(g_bufA + (size_t)gr * astride + kf)
                : make_float4(0.f, 0.f, 0.f, 0.f);
        }
#pragma unroll
        for (int j = 0; j < 2; j++) {
            int r = brow + j * 32, gn = colBase + r;
            bR[j] = *(const float4*)(Wt + (size_t)gn * Kp + k0 + bq * 4);
        }
    }

    for (int c = 0; c < NC; c++) {
        // store prefetched regs to SMEM (with tf32 rounding)
#pragma unroll
        for (int j = 0; j < 4; j++) {
            uint32_t* p = &As[arow + j * 32][aq * 4];
            p[0] = f2tf32(aR[j].x); p[1] = f2tf32(aR[j].y);
            p[2] = f2tf32(aR[j].z); p[3] = f2tf32(aR[j].w);
        }
#pragma unroll
        for (int j = 0; j < 2; j++) {
            uint32_t* p = &Bs[brow + j * 32][bq * 4];
            p[0] = f2tf32(bR[j].x); p[1] = f2tf32(bR[j].y);
            p[2] = f2tf32(bR[j].z); p[3] = f2tf32(bR[j].w);
        }
        __syncthreads();

        // issue global loads for next chunk (overlaps with compute below)
        if (c + 1 < NC) {
            int k0 = (c + 1) * 32;
#pragma unroll
            for (int j = 0; j < 4; j++) {
                int r = arow + j * 32, gr = rowBase + r, kf = k0 + aq * 4;
                aR[j] = (gr < NN && kf < K)
                    ? *(const float4*)(g_bufA + (size_t)gr * astride + kf)
                    : make_float4(0.f, 0.f, 0.f, 0.f);
            }
#pragma unroll
            for (int j = 0; j < 2; j++) {
                int r = brow + j * 32, gn = colBase + r;
                bR[j] = *(const float4*)(Wt + (size_t)gn * Kp + k0 + bq * 4);
            }
        }

        // compute: 4 k-steps of 8
        int g = lane >> 2, cc = lane & 3;
#pragma unroll
        for (int kk = 0; kk < 32; kk += 8) {
            uint32_t af[2][4], bf[4][2];
#pragma unroll
            for (int mi = 0; mi < 2; mi++) {
                int base = wm * 32 + mi * 16 + g;
                af[mi][0] = As[base][kk + cc];
                af[mi][1] = As[base + 8][kk + cc];
                af[mi][2] = As[base][kk + cc + 4];
                af[mi][3] = As[base + 8][kk + cc + 4];
            }
#pragma unroll
            for (int ni = 0; ni < 4; ni++) {
                int nb = wn * 32 + ni * 8 + g;
                bf[ni][0] = Bs[nb][kk + cc];
                bf[ni][1] = Bs[nb][kk + cc + 4];
            }
#pragma unroll
            for (int mi = 0; mi < 2; mi++)
#pragma unroll
                for (int ni = 0; ni < 4; ni++)
                    mma8(acc[mi][ni], af[mi], bf[ni]);
        }
        __syncthreads();
    }

    // epilogue: bias + relu + store + optional sum
    float lsum = 0.f;
    int g = lane >> 2, cc = lane & 3;
#pragma unroll
    for (int mi = 0; mi < 2; mi++) {
        int r0 = rowBase + wm * 32 + mi * 16 + g;
#pragma unroll
        for (int ni = 0; ni < 4; ni++) {
            int c0 = colBase + wn * 32 + ni * 8 + cc * 2;
            if (c0 < FH) {
                float bz0 = bias[c0], bz1 = bias[c0 + 1];
                if (r0 < NN) {
                    float v0 = fmaxf(acc[mi][ni][0] + bz0, 0.f);
                    float v1 = fmaxf(acc[mi][ni][1] + bz1, 0.f);
                    *(float2*)(g_bufB + (size_t)r0 * FH + c0) = make_float2(v0, v1);
                    lsum += v0 + v1;
                }
                if (r0 + 8 < NN) {
                    float v2 = fmaxf(acc[mi][ni][2] + bz0, 0.f);
                    float v3 = fmaxf(acc[mi][ni][3] + bz1, 0.f);
                    *(float2*)(g_bufB + (size_t)(r0 + 8) * FH + c0) = make_float2(v2, v3);
                    lsum += v2 + v3;
                }
            }
        }
    }
    if (dosum) {
#pragma unroll
        for (int o = 16; o > 0; o >>= 1) lsum += __shfl_down_sync(0xffffffffu, lsum, o);
        if (lane == 0) wsum[wid] = lsum;
        __syncthreads();
        if (tid == 0) {
            double tot = 0.0;
#pragma unroll
            for (int w = 0; w < 8; w++) tot += (double)wsum[w];
            atomicAdd(&g_sum, tot);
        }
    }
}

__global__ void k_final(float* __restrict__ out) {
    out[0] = (float)(g_sum / (4.0 * NN * FH));
}

// ---------------- launch -----------------------------------------------------
extern "C" void kernel_launch(void* const* d_in, const int* in_sizes, int n_in,
                              void* d_out, int out_size) {
    const float* X[4];   int nx = 0;
    const int*   EDG[8]; int ne = 0;
    const float* W[3] = {0, 0, 0};
    const float* Bv[3]; int nb = 0;
    int nw2 = 0;
    for (int i = 0; i < n_in; i++) {
        int sz = in_sizes[i];
        if (sz == 6400000)      X[nx++]   = (const float*)d_in[i];
        else if (sz == 800000)  EDG[ne++] = (const int*)d_in[i];
        else if (sz == 38912)   W[0] = (const float*)d_in[i];
        else if (sz == 92416)   { W[1 + nw2] = (const float*)d_in[i]; nw2++; }
        else if (sz == 304)     Bv[nb++] = (const float*)d_in[i];
    }
    float* out = (float*)d_out;

    k_init<<<1, 1>>>();
    k_prep_w<<<(320 * 128 + 255) / 256, 256>>>(W[0], 0, 128, 128);
    k_prep_w<<<(320 * 320 + 255) / 256, 256>>>(W[1], 1, 304, 320);
    k_prep_w<<<(320 * 320 + 255) / 256, 256>>>(W[2], 2, 304, 320);

    // batched CSR build for all 4 graphs
    k_zero<<<dim3(NB, NG), 256>>>();
    k_deg<<<dim3(EE / 256, NG), 256>>>(EDG[0], EDG[1], EDG[2], EDG[3],
                                       EDG[4], EDG[5], EDG[6], EDG[7]);
    k_scan1<<<dim3(NB, NG), 256>>>();
    k_scan2<<<dim3(1, NG), 256>>>();
    k_scan3<<<dim3(NB, NG), 256>>>();
    k_scatter<<<dim3(EE / 256, NG), 256>>>(EDG[0], EDG[1], EDG[2], EDG[3],
                                           EDG[4], EDG[5], EDG[6], EDG[7]);

    dim3 gemmGrid((NN + 127) / 128, 5);  // 391 x 5 (N padded to 320)
    for (int g = 0; g < 4; g++) {
        k_spmm<<<NN, 128>>>(X[g], 1, FI, g);
        k_gemm_mma<<<gemmGrid, 256>>>(Bv[0], 0, 128, 4, 0);
        k_spmm<<<NN, 128>>>(X[g], 0, FH, g);
        k_gemm_mma<<<gemmGrid, 256>>>(Bv[1], 1, 304, 10, 0);
        k_spmm<<<NN, 128>>>(X[g], 0, FH, g);
        k_gemm_mma<<<gemmGrid, 256>>>(Bv[2], 2, 304, 10, 1);
    }
    k_final<<<1, 1>>>(out);
}